// round 16
// baseline (speedup 1.0000x reference)
#include <cuda_runtime.h>
#include <cstdint>

typedef unsigned long long ull;
#define FULLM 0xffffffffu
#define B_    16
#define BV_   64
#define R_    512
#define NCH   32         // chunks per bv (128 rows each)
#define TILE  32
#define NT    4          // tiles per chunk (128 rows / 32)
#define L2E   1.4426950408889634f

static __device__ __forceinline__ ull pk2(float lo, float hi){
    ull r; asm("mov.b64 %0,{%1,%2};" : "=l"(r) : "f"(lo), "f"(hi)); return r;
}
static __device__ __forceinline__ void upk2(ull v, float& lo, float& hi){
    asm("mov.b64 {%0,%1},%2;" : "=f"(lo), "=f"(hi) : "l"(v));
}
static __device__ __forceinline__ ull ffma2(ull a, ull b, ull c){
    ull d; asm("fma.rn.f32x2 %0,%1,%2,%3;" : "=l"(d) : "l"(a), "l"(b), "l"(c)); return d;
}
static __device__ __forceinline__ float ex2f(float v){
    float r; asm("ex2.approx.f32 %0,%1;" : "=f"(r) : "f"(v)); return r;
}
static __device__ __forceinline__ float tanhf_a(float v){
    float r; asm("tanh.approx.f32 %0,%1;" : "=f"(r) : "f"(v)); return r;
}
static __device__ __forceinline__ float sigf(float v){
    return fmaf(0.5f, tanhf_a(0.5f * v), 0.5f);
}

__device__ float d_slot_view[BV_*64];
__device__ float d_slot_attr[B_*8*192];
__device__ float d_h[R_*256];
__device__ float d_qeff[R_*256];
__device__ float d_qscal[R_*2];
__device__ float d_Mq[256*256];
__device__ float d_Wf[256*768];
__device__ float d_whhT[256*768];
__device__ float d_pacc[BV_*NCH*8*256];
__device__ float d_psc [BV_*NCH*8*2];
__device__ float d_Y[R_*256];
__device__ float d_gi[R_*768];
__device__ float d_gh[R_*768];
__device__ float d_xmain[R_*256];
__device__ float d_lnm[R_*256];
__device__ float d_t1[R_*512];
__device__ float d_sfull[R_*256];

static __device__ __forceinline__ void warp_red2(float& a, float& b){
    #pragma unroll
    for (int off = 16; off > 0; off >>= 1){
        a += __shfl_xor_sync(FULLM, a, off);
        b += __shfl_xor_sync(FULLM, b, off);
    }
}

__global__ void k_init(const float* __restrict__ nv, const float* __restrict__ na,
                       const float* __restrict__ vl, const float* __restrict__ vs,
                       const float* __restrict__ al, const float* __restrict__ as_)
{
    int i = blockIdx.x * 256 + threadIdx.x;
    if (i < BV_*64){
        int f = i & 63;
        d_slot_view[i] = fmaf(__expf(vs[f]), nv[i], vl[f]);
    } else {
        int j = i - BV_*64;
        if (j < B_*8*192){
            int f = j % 192;
            d_slot_attr[j] = fmaf(__expf(as_[f]), na[j], al[f]);
        }
    }
}

__global__ void k_transpose(const float* __restrict__ src, float* __restrict__ dst,
                            int Rr, int Cc)
{
    __shared__ float ts[32][33];
    int bx = blockIdx.x * 32, by = blockIdx.y * 32;
    int tx = threadIdx.x & 31, ty = threadIdx.x >> 5;
    #pragma unroll
    for (int j = 0; j < 4; j++){
        int r = by + ty + j*8;
        ts[ty + j*8][tx] = src[r*Cc + bx + tx];
    }
    __syncthreads();
    #pragma unroll
    for (int j = 0; j < 4; j++){
        int c = bx + ty + j*8;
        dst[c*Rr + by + tx] = ts[tx][ty + j*8];
    }
}

__global__ void __launch_bounds__(256)
k_qfused(const float* __restrict__ gq, const float* __restrict__ bq,
         const float* __restrict__ gkv, const float* __restrict__ bkv,
         int from_sfull)
{
    __shared__ float lns[4*256];
    __shared__ float red[8*8];
    int warp = threadIdx.x >> 5, lane = threadIdx.x & 31;
    int r0 = blockIdx.x * 4;
    if (warp < 4){
        int r = r0 + warp, bv = r >> 3, s = r & 7, b = bv >> 2;
        int f0 = lane << 3;
        float v[8];
        if (!from_sfull){
            if (lane < 8){
                const float4* p = (const float4*)(d_slot_view + bv*64 + f0);
                float4 a = p[0], c = p[1];
                v[0]=a.x; v[1]=a.y; v[2]=a.z; v[3]=a.w; v[4]=c.x; v[5]=c.y; v[6]=c.z; v[7]=c.w;
            } else {
                const float4* p = (const float4*)(d_slot_attr + (b*8+s)*192 + f0 - 64);
                float4 a = p[0], c = p[1];
                v[0]=a.x; v[1]=a.y; v[2]=a.z; v[3]=a.w; v[4]=c.x; v[5]=c.y; v[6]=c.z; v[7]=c.w;
            }
        } else {
            #pragma unroll
            for (int i = 0; i < 8; i++) v[i] = 0.f;
            if (lane < 8){
                #pragma unroll
                for (int s2 = 0; s2 < 8; s2++){
                    const float4* p = (const float4*)(d_sfull + (((bv<<3)+s2) << 8) + f0);
                    float4 a = p[0], c = p[1];
                    v[0]+=a.x; v[1]+=a.y; v[2]+=a.z; v[3]+=a.w;
                    v[4]+=c.x; v[5]+=c.y; v[6]+=c.z; v[7]+=c.w;
                }
                #pragma unroll
                for (int i = 0; i < 8; i++) v[i] *= 0.125f;
            } else {
                #pragma unroll
                for (int vv = 0; vv < 4; vv++){
                    const float4* p = (const float4*)(d_sfull + ((((b*4+vv)<<3)+s) << 8) + f0);
                    float4 a = p[0], c = p[1];
                    v[0]+=a.x; v[1]+=a.y; v[2]+=a.z; v[3]+=a.w;
                    v[4]+=c.x; v[5]+=c.y; v[6]+=c.z; v[7]+=c.w;
                }
                #pragma unroll
                for (int i = 0; i < 8; i++) v[i] *= 0.25f;
            }
        }
        float4* hp = (float4*)(d_h + (r << 8) + f0);
        hp[0] = make_float4(v[0],v[1],v[2],v[3]);
        hp[1] = make_float4(v[4],v[5],v[6],v[7]);
        float sx = 0.f, sx2 = 0.f;
        #pragma unroll
        for (int i = 0; i < 8; i++){ sx += v[i]; sx2 = fmaf(v[i], v[i], sx2); }
        warp_red2(sx, sx2);
        float mu = sx * (1.f/256.f);
        float rstd = rsqrtf(fmaf(-mu, mu, sx2*(1.f/256.f)) + 1e-5f);
        const float4* gp = (const float4*)(gq + f0);
        const float4* bp = (const float4*)(bq + f0);
        float4 g0 = gp[0], g1 = gp[1], b0 = bp[0], b1 = bp[1];
        float gg[8] = {g0.x,g0.y,g0.z,g0.w,g1.x,g1.y,g1.z,g1.w};
        float bbv[8] = {b0.x,b0.y,b0.z,b0.w,b1.x,b1.y,b1.z,b1.w};
        #pragma unroll
        for (int i = 0; i < 8; i++)
            lns[warp*256 + f0 + i] = fmaf((v[i]-mu)*rstd, gg[i], bbv[i]);
    }
    __syncthreads();
    int f = threadIdx.x;
    float a0=0.f, a1=0.f, a2=0.f, a3=0.f;
    #pragma unroll 16
    for (int k = 0; k < 256; k++){
        float m = d_Mq[(k << 8) + f];
        a0 = fmaf(m, lns[k],       a0);
        a1 = fmaf(m, lns[256+k],   a1);
        a2 = fmaf(m, lns[512+k],   a2);
        a3 = fmaf(m, lns[768+k],   a3);
    }
    float gcol = gkv[f] * L2E, bcol = bkv[f] * L2E;
    float q0 = a0*gcol, q1 = a1*gcol, q2 = a2*gcol, q3 = a3*gcol;
    d_qeff[((r0+0) << 8) + f] = q0;
    d_qeff[((r0+1) << 8) + f] = q1;
    d_qeff[((r0+2) << 8) + f] = q2;
    d_qeff[((r0+3) << 8) + f] = q3;
    float rv[8] = {q0, a0*bcol, q1, a1*bcol, q2, a2*bcol, q3, a3*bcol};
    #pragma unroll
    for (int off = 16; off > 0; off >>= 1)
        #pragma unroll
        for (int j = 0; j < 8; j++) rv[j] += __shfl_xor_sync(FULLM, rv[j], off);
    if (lane == 0)
        #pragma unroll
        for (int j = 0; j < 8; j++) red[warp*8 + j] = rv[j];
    __syncthreads();
    if (threadIdx.x < 8){
        float t = 0.f;
        #pragma unroll
        for (int w = 0; w < 8; w++) t += red[w*8 + threadIdx.x];
        d_qscal[(r0 + (threadIdx.x >> 1))*2 + (threadIdx.x & 1)] = t;
    }
}

// flash (R13 structure), 128 rows per chunk (NCH=32) for tail fill
__global__ void __launch_bounds__(256, 2)
k_flash(const float* __restrict__ x)
{
    extern __shared__ __align__(16) float smem_f[];
    float* xs = smem_f;
    float* ws = smem_f + 24576;
    float* sS = smem_f + 24576 + 512;

    const int bv = blockIdx.y, chunk = blockIdx.x;
    const int warp = threadIdx.x >> 5, lane = threadIdx.x & 31;
    const float* gx = x + ((size_t)bv << 20) + ((size_t)chunk << 15);

    const int fA = lane << 2;
    const int fB = 128 + (lane << 2);
    const int s0 = (warp & 3) * 2;
    const int rbase = (warp >> 2) * 16;
    const int k7 = lane & 7;
    const int tau = ((k7 & 1) << 2) | (k7 & 2) | ((k7 >> 2) & 1);

    ull qg2[8][4];
    #pragma unroll
    for (int s = 0; s < 8; s++){
        const float* qb_ = d_qeff + (((bv<<3)+s) << 8);
        float4 qa = *(const float4*)(qb_ + fA);
        float4 qc = *(const float4*)(qb_ + fB);
        qg2[s][0] = pk2(qa.x, qa.y); qg2[s][1] = pk2(qa.z, qa.w);
        qg2[s][2] = pk2(qc.x, qc.y); qg2[s][3] = pk2(qc.z, qc.w);
    }
    const float qgs_l = d_qscal[((bv<<3)+tau)*2];
    const float qb_l  = d_qscal[((bv<<3)+tau)*2 + 1];

    ull acc0[4], acc1[4];
    #pragma unroll
    for (int j = 0; j < 4; j++){ acc0[j] = pk2(0.f,0.f); acc1[j] = pk2(0.f,0.f); }
    float S0 = 0.f, S1v = 0.f;

    uint32_t xs_sh = (uint32_t)__cvta_generic_to_shared(xs);
    const int tid16 = threadIdx.x * 16;

    #pragma unroll
    for (int t = 0; t < 2; t++){
        uint32_t dst = xs_sh + t * 32768 + tid16;
        const char* src = (const char*)(gx + t*TILE*256) + tid16;
        #pragma unroll
        for (int i = 0; i < 8; i++)
            asm volatile("cp.async.cg.shared.global [%0],[%1],16;" :: "r"(dst + i*4096), "l"(src + i*4096));
        asm volatile("cp.async.commit_group;");
    }

    const bool b0f = lane & 1, b1f = lane & 2, b2f = lane & 4;

    for (int t = 0; t <= NT; t++){
        if (t < NT){
            if (t + 1 < NT) asm volatile("cp.async.wait_group 1;");
            else            asm volatile("cp.async.wait_group 0;");
        }
        __syncthreads();

        if (t < NT){
            const float* xt = xs + (t % 3) * 8192;
            float* wsw = ws + (t & 1) * 256;
            #pragma unroll
            for (int rr = 0; rr < 4; rr++){
                int r = warp*4 + rr;
                const float* xrow = xt + (r << 8);
                float4 va = *(const float4*)(xrow + fA);
                float4 vb = *(const float4*)(xrow + fB);
                float sx  = ((va.x+va.y)+(va.z+va.w)) + ((vb.x+vb.y)+(vb.z+vb.w));
                float sx2 = va.x*va.x; sx2 = fmaf(va.y,va.y,sx2); sx2 = fmaf(va.z,va.z,sx2);
                sx2 = fmaf(va.w,va.w,sx2); sx2 = fmaf(vb.x,vb.x,sx2); sx2 = fmaf(vb.y,vb.y,sx2);
                sx2 = fmaf(vb.z,vb.z,sx2); sx2 = fmaf(vb.w,vb.w,sx2);
                ull xp[4] = { pk2(va.x,va.y), pk2(va.z,va.w), pk2(vb.x,vb.y), pk2(vb.z,vb.w) };
                float lg[8];
                #pragma unroll
                for (int s = 0; s < 8; s++){
                    ull d = ffma2(qg2[s][0], xp[0], pk2(0.f,0.f));
                    d = ffma2(qg2[s][1], xp[1], d);
                    d = ffma2(qg2[s][2], xp[2], d);
                    d = ffma2(qg2[s][3], xp[3], d);
                    float lo, hi; upk2(d, lo, hi);
                    lg[s] = lo + hi;
                }
                #pragma unroll
                for (int off = 16; off > 0; off >>= 1){
                    sx  += __shfl_xor_sync(FULLM, sx,  off);
                    sx2 += __shfl_xor_sync(FULLM, sx2, off);
                }
                float tv;
                {
                    float s_, q0, q1, q2, q3, r0, r1;
                    s_ = b0f ? lg[0] : lg[4]; q0 = (b0f ? lg[4] : lg[0]) + __shfl_xor_sync(FULLM, s_, 1);
                    s_ = b0f ? lg[1] : lg[5]; q1 = (b0f ? lg[5] : lg[1]) + __shfl_xor_sync(FULLM, s_, 1);
                    s_ = b0f ? lg[2] : lg[6]; q2 = (b0f ? lg[6] : lg[2]) + __shfl_xor_sync(FULLM, s_, 1);
                    s_ = b0f ? lg[3] : lg[7]; q3 = (b0f ? lg[7] : lg[3]) + __shfl_xor_sync(FULLM, s_, 1);
                    s_ = b1f ? q0 : q2; r0 = (b1f ? q2 : q0) + __shfl_xor_sync(FULLM, s_, 2);
                    s_ = b1f ? q1 : q3; r1 = (b1f ? q3 : q1) + __shfl_xor_sync(FULLM, s_, 2);
                    s_ = b2f ? r0 : r1; tv = (b2f ? r1 : r0) + __shfl_xor_sync(FULLM, s_, 4);
                    tv += __shfl_xor_sync(FULLM, tv, 8);
                    tv += __shfl_xor_sync(FULLM, tv, 16);
                }
                float mu = sx * (1.f/256.f);
                float rstd = rsqrtf(fmaf(-mu, mu, sx2*(1.f/256.f)) + 1e-5f);
                float rm = rstd * mu;
                float lgv = fmaf(rstd, tv, fmaf(-rm, qgs_l, qb_l));
                float e = ex2f(lgv);
                float se = e;
                se += __shfl_xor_sync(FULLM, se, 1);
                se += __shfl_xor_sync(FULLM, se, 2);
                se += __shfl_xor_sync(FULLM, se, 4);
                float inv = __fdividef(1.f, se);
                float wv = e * inv;
                float wr = wv * rstd;
                S0 += wv;
                S1v = fmaf(wr, mu, S1v);
                if (lane < 8) wsw[r*8 + tau] = wr;
            }
        }
        if (t > 0){
            const float* xt3 = xs + ((t-1) % 3) * 8192;
            const float* ws3 = ws + ((t-1) & 1) * 256;
            #pragma unroll 4
            for (int rr = 0; rr < 16; rr++){
                int r = rbase + rr;
                float2 wp = *(const float2*)(ws3 + r*8 + s0);
                const float* xrow = xt3 + (r << 8);
                float4 va = *(const float4*)(xrow + fA);
                float4 vb = *(const float4*)(xrow + fB);
                ull xp[4] = { pk2(va.x,va.y), pk2(va.z,va.w), pk2(vb.x,vb.y), pk2(vb.z,vb.w) };
                ull w0 = pk2(wp.x, wp.x), w1 = pk2(wp.y, wp.y);
                #pragma unroll
                for (int j = 0; j < 4; j++){
                    acc0[j] = ffma2(w0, xp[j], acc0[j]);
                    acc1[j] = ffma2(w1, xp[j], acc1[j]);
                }
            }
        }
        __syncthreads();
        if (t + 2 < NT){
            uint32_t dst = xs_sh + ((t+2) % 3) * 32768 + tid16;
            const char* src = (const char*)(gx + (t+2)*TILE*256) + tid16;
            #pragma unroll
            for (int i = 0; i < 8; i++)
                asm volatile("cp.async.cg.shared.global [%0],[%1],16;" :: "r"(dst + i*4096), "l"(src + i*4096));
            asm volatile("cp.async.commit_group;");
        }
    }

    float* mg = smem_f;
    if (warp >= 4){
        float o[8];
        #pragma unroll
        for (int j = 0; j < 4; j++) upk2(acc0[j], o[2*j], o[2*j+1]);
        float* p = mg + ((warp-4)*2 + 0)*256;
        *(float4*)(p + fA) = make_float4(o[0],o[1],o[2],o[3]);
        *(float4*)(p + fB) = make_float4(o[4],o[5],o[6],o[7]);
        #pragma unroll
        for (int j = 0; j < 4; j++) upk2(acc1[j], o[2*j], o[2*j+1]);
        p = mg + ((warp-4)*2 + 1)*256;
        *(float4*)(p + fA) = make_float4(o[0],o[1],o[2],o[3]);
        *(float4*)(p + fB) = make_float4(o[4],o[5],o[6],o[7]);
    }
    if (lane < 8){
        sS[warp*16 + tau*2]     = S0;
        sS[warp*16 + tau*2 + 1] = S1v;
    }
    __syncthreads();
    if (warp < 4){
        const int pbase = ((bv*NCH + chunk) << 3);
        float o[8];
        #pragma unroll
        for (int j = 0; j < 4; j++) upk2(acc0[j], o[2*j], o[2*j+1]);
        const float* pm = mg + (warp*2 + 0)*256;
        {
            float4 a = *(const float4*)(pm + fA), b = *(const float4*)(pm + fB);
            o[0]+=a.x; o[1]+=a.y; o[2]+=a.z; o[3]+=a.w;
            o[4]+=b.x; o[5]+=b.y; o[6]+=b.z; o[7]+=b.w;
        }
        float* dst = d_pacc + ((pbase + s0) << 8);
        *(float4*)(dst + fA) = make_float4(o[0],o[1],o[2],o[3]);
        *(float4*)(dst + fB) = make_float4(o[4],o[5],o[6],o[7]);
        #pragma unroll
        for (int j = 0; j < 4; j++) upk2(acc1[j], o[2*j], o[2*j+1]);
        pm = mg + (warp*2 + 1)*256;
        {
            float4 a = *(const float4*)(pm + fA), b = *(const float4*)(pm + fB);
            o[0]+=a.x; o[1]+=a.y; o[2]+=a.z; o[3]+=a.w;
            o[4]+=b.x; o[5]+=b.y; o[6]+=b.z; o[7]+=b.w;
        }
        dst = d_pacc + ((pbase + s0 + 1) << 8);
        *(float4*)(dst + fA) = make_float4(o[0],o[1],o[2],o[3]);
        *(float4*)(dst + fB) = make_float4(o[4],o[5],o[6],o[7]);
    }
    if (warp == 0 && lane < 8){
        float t0 = 0.f, t1 = 0.f;
        #pragma unroll
        for (int u = 0; u < 8; u++){ t0 += sS[u*16 + lane*2]; t1 += sS[u*16 + lane*2 + 1]; }
        int idx = ((bv*NCH + chunk)*8 + lane)*2;
        d_psc[idx] = t0; d_psc[idx+1] = t1;
    }
}

__global__ void k_combine(const float* __restrict__ g, const float* __restrict__ bb)
{
    int r = blockIdx.x, bv = r >> 3, s = r & 7, f = threadIdx.x;
    const float* pa = d_pacc + ((bv*NCH*8 + s) << 8) + f;
    float X = 0.f;
    #pragma unroll 8
    for (int c = 0; c < NCH; c++) X += pa[c * 2048];
    const float* ps = d_psc + (bv*NCH*8 + s)*2;
    float s0 = 0.f, s1 = 0.f;
    #pragma unroll 8
    for (int c = 0; c < NCH; c++){ s0 += ps[c*16]; s1 += ps[c*16+1]; }
    float inv = __fdividef(1.f, s0);
    d_Y[(r << 8) + f] = fmaf(g[f], (X - s1) * inv, bb[f]);
}

// 32x64 GEMM, 128 threads, 4x4/thread, register-prefetch pipelined K-loop
template<int TRANSB, int RELU>
__global__ void __launch_bounds__(128)
k_gemm(int M, int N, int K,
       const float* __restrict__ A, int lda,
       const float* __restrict__ B, int ldb,
       float* __restrict__ C, int ldc,
       const float* __restrict__ bias,
       const float* __restrict__ resid, int ldr, float alpha)
{
    __shared__ __align__(16) float As[32][36];
    __shared__ __align__(16) float Bs[32][68];
    const int bm = blockIdx.y * 32, bn = blockIdx.x * 64;
    const int tid = threadIdx.x, tx = tid & 15, ty = tid >> 4;
    float acc[4][4] = {};

    const int am = tid & 31, ak8 = (tid >> 5) << 3;
    const float* aptr = A + (size_t)(bm + am)*lda + ak8;
    const int bn1 = tid >> 1, bkc = (tid & 1) << 4;
    const int bkk = tid >> 2, bnc = (tid & 3) << 4;
    const float* bptr = TRANSB ? (B + (size_t)(bn + bn1)*ldb + bkc)
                               : (B + (size_t)bkk*ldb + bn + bnc);

    float4 pa0, pa1, pb[4];
    pa0 = *(const float4*)aptr; pa1 = *(const float4*)(aptr + 4);
    #pragma unroll
    for (int j = 0; j < 4; j++) pb[j] = *(const float4*)(bptr + j*4);

    const int KT = K >> 5;
    for (int t = 0; t < KT; t++){
        As[ak8+0][am]=pa0.x; As[ak8+1][am]=pa0.y; As[ak8+2][am]=pa0.z; As[ak8+3][am]=pa0.w;
        As[ak8+4][am]=pa1.x; As[ak8+5][am]=pa1.y; As[ak8+6][am]=pa1.z; As[ak8+7][am]=pa1.w;
        if (TRANSB){
            #pragma unroll
            for (int j = 0; j < 4; j++){
                Bs[bkc+j*4+0][bn1]=pb[j].x; Bs[bkc+j*4+1][bn1]=pb[j].y;
                Bs[bkc+j*4+2][bn1]=pb[j].z; Bs[bkc+j*4+3][bn1]=pb[j].w;
            }
        } else {
            #pragma unroll
            for (int j = 0; j < 4; j++)
                *(float4*)&Bs[bkk][bnc + j*4] = pb[j];
        }
        __syncthreads();
        if (t + 1 < KT){
            const float* an = aptr + (t+1)*32;
            pa0 = *(const float4*)an; pa1 = *(const float4*)(an + 4);
            if (TRANSB){
                const float* bn_ = bptr + (t+1)*32;
                #pragma unroll
                for (int j = 0; j < 4; j++) pb[j] = *(const float4*)(bn_ + j*4);
            } else {
                const float* bn_ = bptr + (size_t)(t+1)*32*ldb;
                #pragma unroll
                for (int j = 0; j < 4; j++) pb[j] = *(const float4*)(bn_ + j*4);
            }
        }
        #pragma unroll
        for (int kk = 0; kk < 32; kk++){
            float4 a = *(const float4*)&As[kk][ty << 2];
            float4 b = *(const float4*)&Bs[kk][tx << 2];
            float av[4] = {a.x,a.y,a.z,a.w}, bv[4] = {b.x,b.y,b.z,b.w};
            #pragma unroll
            for (int i = 0; i < 4; i++)
                #pragma unroll
                for (int j = 0; j < 4; j++)
                    acc[i][j] = fmaf(av[i], bv[j], acc[i][j]);
        }
        __syncthreads();
    }
    #pragma unroll
    for (int i = 0; i < 4; i++){
        int row = bm + (ty << 2) + i;
        int col = bn + (tx << 2);
        float4 v = make_float4(acc[i][0]*alpha, acc[i][1]*alpha, acc[i][2]*alpha, acc[i][3]*alpha);
        if (bias){
            float4 bb4 = *(const float4*)(bias + col);
            v.x += bb4.x; v.y += bb4.y; v.z += bb4.z; v.w += bb4.w;
        }
        if (resid){
            float4 rr4 = *(const float4*)(resid + (size_t)row*ldr + col);
            v.x += rr4.x; v.y += rr4.y; v.z += rr4.z; v.w += rr4.w;
        }
        if (RELU){
            v.x = fmaxf(v.x, 0.f); v.y = fmaxf(v.y, 0.f);
            v.z = fmaxf(v.z, 0.f); v.w = fmaxf(v.w, 0.f);
        }
        *(float4*)(C + (size_t)row*ldc + col) = v;
    }
}

// z-batched dual GEMM: 64x64 tiles, 256 threads, 4x4/thread, reg-prefetch pipeline
__global__ void __launch_bounds__(256)
k_gemm_dual(const float* __restrict__ A0, const float* __restrict__ B0,
            float* __restrict__ C0, const float* __restrict__ bias0,
            const float* __restrict__ A1, const float* __restrict__ B1,
            float* __restrict__ C1, const float* __restrict__ bias1)
{
    const int z = blockIdx.z;
    const float* A = z ? A1 : A0;
    const float* B = z ? B1 : B0;
    float* C = z ? C1 : C0;
    const float* bias = z ? bias1 : bias0;
    const int lda = 256, ldb = 768, ldc = 768;

    __shared__ __align__(16) float As[32][68];
    __shared__ __align__(16) float Bs[32][68];
    const int bm = blockIdx.y * 64, bn = blockIdx.x * 64;
    const int tid = threadIdx.x, tx = tid & 15, ty = tid >> 4;
    float acc[4][4] = {};

    const int am = tid & 63, ak8 = (tid >> 6) << 3;
    const float* aptr = A + (size_t)(bm + am)*lda + ak8;
    const int bkk = tid >> 3, bnc = (tid & 7) << 3;
    const float* bptr = B + (size_t)bkk*ldb + bn + bnc;

    float4 pa0, pa1, pb0, pb1;
    pa0 = *(const float4*)aptr; pa1 = *(const float4*)(aptr + 4);
    pb0 = *(const float4*)bptr; pb1 = *(const float4*)(bptr + 4);

    for (int t = 0; t < 8; t++){
        As[ak8+0][am]=pa0.x; As[ak8+1][am]=pa0.y; As[ak8+2][am]=pa0.z; As[ak8+3][am]=pa0.w;
        As[ak8+4][am]=pa1.x; As[ak8+5][am]=pa1.y; As[ak8+6][am]=pa1.z; As[ak8+7][am]=pa1.w;
        *(float4*)&Bs[bkk][bnc]     = pb0;
        *(float4*)&Bs[bkk][bnc + 4] = pb1;
        __syncthreads();
        if (t + 1 < 8){
            const float* an = aptr + (t+1)*32;
            pa0 = *(const float4*)an; pa1 = *(const float4*)(an + 4);
            const float* bn_ = bptr + (size_t)(t+1)*32*ldb;
            pb0 = *(const float4*)bn_; pb1 = *(const float4*)(bn_ + 4);
        }
        #pragma unroll
        for (int kk = 0; kk < 32; kk++){
            float4 a = *(const float4*)&As[kk][ty << 2];
            float4 b = *(const float4*)&Bs[kk][tx << 2];
            float av[4] = {a.x,a.y,a.z,a.w}, bv[4] = {b.x,b.y,b.z,b.w};
            #pragma unroll
            for (int i = 0; i < 4; i++)
                #pragma unroll
                for (int j = 0; j < 4; j++)
                    acc[i][j] = fmaf(av[i], bv[j], acc[i][j]);
        }
        __syncthreads();
    }
    #pragma unroll
    for (int i = 0; i < 4; i++){
        int row = bm + (ty << 2) + i;
        int col = bn + (tx << 2);
        float4 bb4 = *(const float4*)(bias + col);
        float4 v = make_float4(acc[i][0]+bb4.x, acc[i][1]+bb4.y, acc[i][2]+bb4.z, acc[i][3]+bb4.w);
        *(float4*)(C + (size_t)row*ldc + col) = v;
    }
}

__global__ void k_gru(const float* __restrict__ g, const float* __restrict__ bb)
{
    int r = blockIdx.x * 4 + (threadIdx.x >> 5);
    int lane = threadIdx.x & 31, f0 = lane << 3;
    int base = r * 768;
    float gi0[8], gi1[8], gi2[8], gh0[8], gh1[8], gh2[8], hv[8];
    #pragma unroll
    for (int c = 0; c < 2; c++){
        float4 t;
        t = *(const float4*)(d_gi + base + f0 + c*4);        gi0[c*4]=t.x; gi0[c*4+1]=t.y; gi0[c*4+2]=t.z; gi0[c*4+3]=t.w;
        t = *(const float4*)(d_gi + base + 256 + f0 + c*4);  gi1[c*4]=t.x; gi1[c*4+1]=t.y; gi1[c*4+2]=t.z; gi1[c*4+3]=t.w;
        t = *(const float4*)(d_gi + base + 512 + f0 + c*4);  gi2[c*4]=t.x; gi2[c*4+1]=t.y; gi2[c*4+2]=t.z; gi2[c*4+3]=t.w;
        t = *(const float4*)(d_gh + base + f0 + c*4);        gh0[c*4]=t.x; gh0[c*4+1]=t.y; gh0[c*4+2]=t.z; gh0[c*4+3]=t.w;
        t = *(const float4*)(d_gh + base + 256 + f0 + c*4);  gh1[c*4]=t.x; gh1[c*4+1]=t.y; gh1[c*4+2]=t.z; gh1[c*4+3]=t.w;
        t = *(const float4*)(d_gh + base + 512 + f0 + c*4);  gh2[c*4]=t.x; gh2[c*4+1]=t.y; gh2[c*4+2]=t.z; gh2[c*4+3]=t.w;
        t = *(const float4*)(d_h + (r << 8) + f0 + c*4);     hv[c*4]=t.x; hv[c*4+1]=t.y; hv[c*4+2]=t.z; hv[c*4+3]=t.w;
    }
    float xm[8], sx = 0.f, sx2 = 0.f;
    #pragma unroll
    for (int i = 0; i < 8; i++){
        float rg = sigf(gi0[i] + gh0[i]);
        float z  = sigf(gi1[i] + gh1[i]);
        float nn = tanhf_a(fmaf(rg, gh2[i], gi2[i]));
        xm[i] = fmaf(z, hv[i], (1.f - z) * nn);
        sx += xm[i]; sx2 = fmaf(xm[i], xm[i], sx2);
    }
    float4* xp = (float4*)(d_xmain + (r << 8) + f0);
    xp[0] = make_float4(xm[0],xm[1],xm[2],xm[3]);
    xp[1] = make_float4(xm[4],xm[5],xm[6],xm[7]);
    warp_red2(sx, sx2);
    float mu = sx * (1.f/256.f);
    float rstd = rsqrtf(fmaf(-mu, mu, sx2*(1.f/256.f)) + 1e-5f);
    const float4* gp = (const float4*)(g + f0);
    const float4* bp = (const float4*)(bb + f0);
    float4 ga = gp[0], gb2 = gp[1], ba = bp[0], bb2 = bp[1];
    float gg[8] = {ga.x,ga.y,ga.z,ga.w,gb2.x,gb2.y,gb2.z,gb2.w};
    float bv[8] = {ba.x,ba.y,ba.z,ba.w,bb2.x,bb2.y,bb2.z,bb2.w};
    float o[8];
    #pragma unroll
    for (int i = 0; i < 8; i++) o[i] = fmaf((xm[i]-mu)*rstd, gg[i], bv[i]);
    float4* lp = (float4*)(d_lnm + (r << 8) + f0);
    lp[0] = make_float4(o[0],o[1],o[2],o[3]);
    lp[1] = make_float4(o[4],o[5],o[6],o[7]);
}

__global__ void k_reduce(float* dst_view, float* dst_attr)
{
    int i = blockIdx.x * 256 + threadIdx.x;
    if (i < BV_*64){
        int bv = i >> 6, f = i & 63;
        float sum = 0.f;
        #pragma unroll
        for (int s = 0; s < 8; s++) sum += d_sfull[(((bv<<3)+s) << 8) + f];
        dst_view[i] = sum * 0.125f;
    } else {
        int j = i - BV_*64;
        if (j < B_*8*192){
            int bs = j / 192, f = j % 192;
            int b = bs >> 3, s = bs & 7;
            float sum = 0.f;
            #pragma unroll
            for (int v = 0; v < 4; v++) sum += d_sfull[(((b*4+v)*8+s) << 8) + 64 + f];
            dst_attr[j] = sum * 0.25f;
        }
    }
}

extern "C" void kernel_launch(void* const* d_in, const int* in_sizes, int n_in,
                              void* d_out, int out_size)
{
    (void)in_sizes; (void)n_in; (void)out_size;
    const float* x   = (const float*)d_in[0];
    const float* nv  = (const float*)d_in[1];
    const float* na  = (const float*)d_in[2];
    const float* vl  = (const float*)d_in[3];
    const float* vs  = (const float*)d_in[4];
    const float* al  = (const float*)d_in[5];
    const float* as_ = (const float*)d_in[6];
    const float* ln_kv_g = (const float*)d_in[7];
    const float* ln_kv_b = (const float*)d_in[8];
    const float* W_kv    = (const float*)d_in[9];
    const float* ln_q_g  = (const float*)d_in[10];
    const float* ln_q_b  = (const float*)d_in[11];
    const float* W_qry   = (const float*)d_in[12];
    const float* w_ih    = (const float*)d_in[13];
    const float* w_hh    = (const float*)d_in[14];
    const float* b_ih    = (const float*)d_in[15];
    const float* b_hh    = (const float*)d_in[16];
    const float* ln_r_g  = (const float*)d_in[17];
    const float* ln_r_b  = (const float*)d_in[18];
    const float* W_r1    = (const float*)d_in[19];
    const float* b_r1    = (const float*)d_in[20];
    const float* W_r2    = (const float*)d_in[21];
    const float* b_r2    = (const float*)d_in[22];
    float* out_view = (float*)d_out;
    float* out_attr = out_view + BV_*64;

    float* Mq;    cudaGetSymbolAddress((void**)&Mq, d_Mq);
    float* Wf;    cudaGetSymbolAddress((void**)&Wf, d_Wf);
    float* whhT;  cudaGetSymbolAddress((void**)&whhT, d_whhT);
    float* Y;     cudaGetSymbolAddress((void**)&Y, d_Y);
    float* gi;    cudaGetSymbolAddress((void**)&gi, d_gi);
    float* gh;    cudaGetSymbolAddress((void**)&gh, d_gh);
    float* h;     cudaGetSymbolAddress((void**)&h, d_h);
    float* lnm;   cudaGetSymbolAddress((void**)&lnm, d_lnm);
    float* t1;    cudaGetSymbolAddress((void**)&t1, d_t1);
    float* sfull; cudaGetSymbolAddress((void**)&sfull, d_sfull);
    float* xmain; cudaGetSymbolAddress((void**)&xmain, d_xmain);

    const int FLASH_SMEM = (24576 + 512 + 128) * 4;
    static int smem_set = 0;
    if (!smem_set){
        cudaFuncSetAttribute(k_flash, cudaFuncAttributeMaxDynamicSharedMemorySize, FLASH_SMEM);
        smem_set = 1;
    }

    const float coef = 0.08838834764831845f;   // 1/sqrt(128)

    k_init<<<112,256>>>(nv, na, vl, vs, al, as_);
    k_gemm<1,0><<<dim3(4,8),128>>>(256,256,128, W_qry,128, W_kv,384, Mq,256, nullptr, nullptr,0, coef);

    for (int step = 0; step < 3; step++){
        k_qfused<<<128,256>>>(ln_q_g, ln_q_b, ln_kv_g, ln_kv_b, step > 0 ? 1 : 0);
        k_flash<<<dim3(NCH,64),256,FLASH_SMEM>>>(x);
        if (step == 0){
            k_gemm<1,0><<<dim3(12,8),128>>>(256,768,256, W_kv+128,384, w_ih,256, Wf,768, nullptr, nullptr,0, 1.f);
            k_transpose<<<dim3(8,24),256>>>(w_hh, whhT, 768, 256);
        }
        k_combine<<<512,256>>>(ln_kv_g, ln_kv_b);
        k_gemm_dual<<<dim3(12,8,2),256>>>(Y, Wf, gi, b_ih, h, whhT, gh, b_hh);
        k_gru<<<128,128>>>(ln_r_g, ln_r_b);
        k_gemm<0,1><<<dim3(8,16),128>>>(512,512,256, lnm,256, W_r1,512, t1,512, b_r1, nullptr,0, 1.f);
        k_gemm<0,0><<<dim3(4,16),128>>>(512,256,512, t1,512, W_r2,256, sfull,256, b_r2, xmain,256, 1.f);
    }
    k_reduce<<<112,256>>>(out_view, out_attr);
}

// round 17
// speedup vs baseline: 1.0568x; 1.0568x over previous
#include <cuda_runtime.h>
#include <cstdint>

typedef unsigned long long ull;
#define FULLM 0xffffffffu
#define B_    16
#define BV_   64
#define R_    512
#define NCH   16
#define TILE  32
#define NT    8
#define L2E   1.4426950408889634f

static __device__ __forceinline__ ull pk2(float lo, float hi){
    ull r; asm("mov.b64 %0,{%1,%2};" : "=l"(r) : "f"(lo), "f"(hi)); return r;
}
static __device__ __forceinline__ void upk2(ull v, float& lo, float& hi){
    asm("mov.b64 {%0,%1},%2;" : "=f"(lo), "=f"(hi) : "l"(v));
}
static __device__ __forceinline__ ull ffma2(ull a, ull b, ull c){
    ull d; asm("fma.rn.f32x2 %0,%1,%2,%3;" : "=l"(d) : "l"(a), "l"(b), "l"(c)); return d;
}
static __device__ __forceinline__ float ex2f(float v){
    float r; asm("ex2.approx.f32 %0,%1;" : "=f"(r) : "f"(v)); return r;
}
static __device__ __forceinline__ float tanhf_a(float v){
    float r; asm("tanh.approx.f32 %0,%1;" : "=f"(r) : "f"(v)); return r;
}
static __device__ __forceinline__ float sigf(float v){
    return fmaf(0.5f, tanhf_a(0.5f * v), 0.5f);
}

__device__ float d_slot_view[BV_*64];
__device__ float d_slot_attr[B_*8*192];
__device__ float d_h[R_*256];
__device__ float d_qeff[R_*256];
__device__ float d_qscal[R_*2];
__device__ float d_Mq[256*256];
__device__ float d_Wf[256*768];
__device__ float d_whhT[256*768];
__device__ float d_pacc[BV_*NCH*8*256];
__device__ float d_psc [BV_*NCH*8*2];
__device__ float d_Y[R_*256];
__device__ float d_gi[R_*768];
__device__ float d_gh[R_*768];
__device__ float d_xmain[R_*256];
__device__ float d_lnm[R_*256];
__device__ float d_t1[R_*512];
__device__ float d_sfull[R_*256];

static __device__ __forceinline__ void warp_red2(float& a, float& b){
    #pragma unroll
    for (int off = 16; off > 0; off >>= 1){
        a += __shfl_xor_sync(FULLM, a, off);
        b += __shfl_xor_sync(FULLM, b, off);
    }
}

__global__ void k_init(const float* __restrict__ nv, const float* __restrict__ na,
                       const float* __restrict__ vl, const float* __restrict__ vs,
                       const float* __restrict__ al, const float* __restrict__ as_)
{
    int i = blockIdx.x * 256 + threadIdx.x;
    if (i < BV_*64){
        int f = i & 63;
        d_slot_view[i] = fmaf(__expf(vs[f]), nv[i], vl[f]);
    } else {
        int j = i - BV_*64;
        if (j < B_*8*192){
            int f = j % 192;
            d_slot_attr[j] = fmaf(__expf(as_[f]), na[j], al[f]);
        }
    }
}

__global__ void k_transpose(const float* __restrict__ src, float* __restrict__ dst,
                            int Rr, int Cc)
{
    __shared__ float ts[32][33];
    int bx = blockIdx.x * 32, by = blockIdx.y * 32;
    int tx = threadIdx.x & 31, ty = threadIdx.x >> 5;
    #pragma unroll
    for (int j = 0; j < 4; j++){
        int r = by + ty + j*8;
        ts[ty + j*8][tx] = src[r*Cc + bx + tx];
    }
    __syncthreads();
    #pragma unroll
    for (int j = 0; j < 4; j++){
        int c = bx + ty + j*8;
        dst[c*Rr + by + tx] = ts[tx][ty + j*8];
    }
}

__global__ void __launch_bounds__(256)
k_qfused(const float* __restrict__ gq, const float* __restrict__ bq,
         const float* __restrict__ gkv, const float* __restrict__ bkv,
         int from_sfull)
{
    __shared__ float lns[4*256];
    __shared__ float red[8*8];
    int warp = threadIdx.x >> 5, lane = threadIdx.x & 31;
    int r0 = blockIdx.x * 4;
    if (warp < 4){
        int r = r0 + warp, bv = r >> 3, s = r & 7, b = bv >> 2;
        int f0 = lane << 3;
        float v[8];
        if (!from_sfull){
            if (lane < 8){
                const float4* p = (const float4*)(d_slot_view + bv*64 + f0);
                float4 a = p[0], c = p[1];
                v[0]=a.x; v[1]=a.y; v[2]=a.z; v[3]=a.w; v[4]=c.x; v[5]=c.y; v[6]=c.z; v[7]=c.w;
            } else {
                const float4* p = (const float4*)(d_slot_attr + (b*8+s)*192 + f0 - 64);
                float4 a = p[0], c = p[1];
                v[0]=a.x; v[1]=a.y; v[2]=a.z; v[3]=a.w; v[4]=c.x; v[5]=c.y; v[6]=c.z; v[7]=c.w;
            }
        } else {
            #pragma unroll
            for (int i = 0; i < 8; i++) v[i] = 0.f;
            if (lane < 8){
                #pragma unroll
                for (int s2 = 0; s2 < 8; s2++){
                    const float4* p = (const float4*)(d_sfull + (((bv<<3)+s2) << 8) + f0);
                    float4 a = p[0], c = p[1];
                    v[0]+=a.x; v[1]+=a.y; v[2]+=a.z; v[3]+=a.w;
                    v[4]+=c.x; v[5]+=c.y; v[6]+=c.z; v[7]+=c.w;
                }
                #pragma unroll
                for (int i = 0; i < 8; i++) v[i] *= 0.125f;
            } else {
                #pragma unroll
                for (int vv = 0; vv < 4; vv++){
                    const float4* p = (const float4*)(d_sfull + ((((b*4+vv)<<3)+s) << 8) + f0);
                    float4 a = p[0], c = p[1];
                    v[0]+=a.x; v[1]+=a.y; v[2]+=a.z; v[3]+=a.w;
                    v[4]+=c.x; v[5]+=c.y; v[6]+=c.z; v[7]+=c.w;
                }
                #pragma unroll
                for (int i = 0; i < 8; i++) v[i] *= 0.25f;
            }
        }
        float4* hp = (float4*)(d_h + (r << 8) + f0);
        hp[0] = make_float4(v[0],v[1],v[2],v[3]);
        hp[1] = make_float4(v[4],v[5],v[6],v[7]);
        float sx = 0.f, sx2 = 0.f;
        #pragma unroll
        for (int i = 0; i < 8; i++){ sx += v[i]; sx2 = fmaf(v[i], v[i], sx2); }
        warp_red2(sx, sx2);
        float mu = sx * (1.f/256.f);
        float rstd = rsqrtf(fmaf(-mu, mu, sx2*(1.f/256.f)) + 1e-5f);
        const float4* gp = (const float4*)(gq + f0);
        const float4* bp = (const float4*)(bq + f0);
        float4 g0 = gp[0], g1 = gp[1], b0 = bp[0], b1 = bp[1];
        float gg[8] = {g0.x,g0.y,g0.z,g0.w,g1.x,g1.y,g1.z,g1.w};
        float bbv[8] = {b0.x,b0.y,b0.z,b0.w,b1.x,b1.y,b1.z,b1.w};
        #pragma unroll
        for (int i = 0; i < 8; i++)
            lns[warp*256 + f0 + i] = fmaf((v[i]-mu)*rstd, gg[i], bbv[i]);
    }
    __syncthreads();
    int f = threadIdx.x;
    float a0=0.f, a1=0.f, a2=0.f, a3=0.f;
    #pragma unroll 16
    for (int k = 0; k < 256; k++){
        float m = d_Mq[(k << 8) + f];
        a0 = fmaf(m, lns[k],       a0);
        a1 = fmaf(m, lns[256+k],   a1);
        a2 = fmaf(m, lns[512+k],   a2);
        a3 = fmaf(m, lns[768+k],   a3);
    }
    float gcol = gkv[f] * L2E, bcol = bkv[f] * L2E;
    float q0 = a0*gcol, q1 = a1*gcol, q2 = a2*gcol, q3 = a3*gcol;
    d_qeff[((r0+0) << 8) + f] = q0;
    d_qeff[((r0+1) << 8) + f] = q1;
    d_qeff[((r0+2) << 8) + f] = q2;
    d_qeff[((r0+3) << 8) + f] = q3;
    float rv[8] = {q0, a0*bcol, q1, a1*bcol, q2, a2*bcol, q3, a3*bcol};
    #pragma unroll
    for (int off = 16; off > 0; off >>= 1)
        #pragma unroll
        for (int j = 0; j < 8; j++) rv[j] += __shfl_xor_sync(FULLM, rv[j], off);
    if (lane == 0)
        #pragma unroll
        for (int j = 0; j < 8; j++) red[warp*8 + j] = rv[j];
    __syncthreads();
    if (threadIdx.x < 8){
        float t = 0.f;
        #pragma unroll
        for (int w = 0; w < 8; w++) t += red[w*8 + threadIdx.x];
        d_qscal[(r0 + (threadIdx.x >> 1))*2 + (threadIdx.x & 1)] = t;
    }
}

// flash (R13/R15 proven version, NCH=16)
__global__ void __launch_bounds__(256, 2)
k_flash(const float* __restrict__ x)
{
    extern __shared__ __align__(16) float smem_f[];
    float* xs = smem_f;
    float* ws = smem_f + 24576;
    float* sS = smem_f + 24576 + 512;

    const int bv = blockIdx.y, chunk = blockIdx.x;
    const int warp = threadIdx.x >> 5, lane = threadIdx.x & 31;
    const float* gx = x + ((size_t)bv << 20) + ((size_t)chunk << 16);

    const int fA = lane << 2;
    const int fB = 128 + (lane << 2);
    const int s0 = (warp & 3) * 2;
    const int rbase = (warp >> 2) * 16;
    const int k7 = lane & 7;
    const int tau = ((k7 & 1) << 2) | (k7 & 2) | ((k7 >> 2) & 1);

    ull qg2[8][4];
    #pragma unroll
    for (int s = 0; s < 8; s++){
        const float* qb_ = d_qeff + (((bv<<3)+s) << 8);
        float4 qa = *(const float4*)(qb_ + fA);
        float4 qc = *(const float4*)(qb_ + fB);
        qg2[s][0] = pk2(qa.x, qa.y); qg2[s][1] = pk2(qa.z, qa.w);
        qg2[s][2] = pk2(qc.x, qc.y); qg2[s][3] = pk2(qc.z, qc.w);
    }
    const float qgs_l = d_qscal[((bv<<3)+tau)*2];
    const float qb_l  = d_qscal[((bv<<3)+tau)*2 + 1];

    ull acc0[4], acc1[4];
    #pragma unroll
    for (int j = 0; j < 4; j++){ acc0[j] = pk2(0.f,0.f); acc1[j] = pk2(0.f,0.f); }
    float S0 = 0.f, S1v = 0.f;

    uint32_t xs_sh = (uint32_t)__cvta_generic_to_shared(xs);
    const int tid16 = threadIdx.x * 16;

    #pragma unroll
    for (int t = 0; t < 2; t++){
        uint32_t dst = xs_sh + t * 32768 + tid16;
        const char* src = (const char*)(gx + t*TILE*256) + tid16;
        #pragma unroll
        for (int i = 0; i < 8; i++)
            asm volatile("cp.async.cg.shared.global [%0],[%1],16;" :: "r"(dst + i*4096), "l"(src + i*4096));
        asm volatile("cp.async.commit_group;");
    }

    const bool b0f = lane & 1, b1f = lane & 2, b2f = lane & 4;

    for (int t = 0; t <= NT; t++){
        if (t < NT){
            if (t + 1 < NT) asm volatile("cp.async.wait_group 1;");
            else            asm volatile("cp.async.wait_group 0;");
        }
        __syncthreads();

        if (t < NT){
            const float* xt = xs + (t % 3) * 8192;
            float* wsw = ws + (t & 1) * 256;
            #pragma unroll
            for (int rr = 0; rr < 4; rr++){
                int r = warp*4 + rr;
                const float* xrow = xt + (r << 8);
                float4 va = *(const float4*)(xrow + fA);
                float4 vb = *(const float4*)(xrow + fB);
                float sx  = ((va.x+va.y)+(va.z+va.w)) + ((vb.x+vb.y)+(vb.z+vb.w));
                float sx2 = va.x*va.x; sx2 = fmaf(va.y,va.y,sx2); sx2 = fmaf(va.z,va.z,sx2);
                sx2 = fmaf(va.w,va.w,sx2); sx2 = fmaf(vb.x,vb.x,sx2); sx2 = fmaf(vb.y,vb.y,sx2);
                sx2 = fmaf(vb.z,vb.z,sx2); sx2 = fmaf(vb.w,vb.w,sx2);
                ull xp[4] = { pk2(va.x,va.y), pk2(va.z,va.w), pk2(vb.x,vb.y), pk2(vb.z,vb.w) };
                float lg[8];
                #pragma unroll
                for (int s = 0; s < 8; s++){
                    ull d = ffma2(qg2[s][0], xp[0], pk2(0.f,0.f));
                    d = ffma2(qg2[s][1], xp[1], d);
                    d = ffma2(qg2[s][2], xp[2], d);
                    d = ffma2(qg2[s][3], xp[3], d);
                    float lo, hi; upk2(d, lo, hi);
                    lg[s] = lo + hi;
                }
                #pragma unroll
                for (int off = 16; off > 0; off >>= 1){
                    sx  += __shfl_xor_sync(FULLM, sx,  off);
                    sx2 += __shfl_xor_sync(FULLM, sx2, off);
                }
                float tv;
                {
                    float s_, q0, q1, q2, q3, r0, r1;
                    s_ = b0f ? lg[0] : lg[4]; q0 = (b0f ? lg[4] : lg[0]) + __shfl_xor_sync(FULLM, s_, 1);
                    s_ = b0f ? lg[1] : lg[5]; q1 = (b0f ? lg[5] : lg[1]) + __shfl_xor_sync(FULLM, s_, 1);
                    s_ = b0f ? lg[2] : lg[6]; q2 = (b0f ? lg[6] : lg[2]) + __shfl_xor_sync(FULLM, s_, 1);
                    s_ = b0f ? lg[3] : lg[7]; q3 = (b0f ? lg[7] : lg[3]) + __shfl_xor_sync(FULLM, s_, 1);
                    s_ = b1f ? q0 : q2; r0 = (b1f ? q2 : q0) + __shfl_xor_sync(FULLM, s_, 2);
                    s_ = b1f ? q1 : q3; r1 = (b1f ? q3 : q1) + __shfl_xor_sync(FULLM, s_, 2);
                    s_ = b2f ? r0 : r1; tv = (b2f ? r1 : r0) + __shfl_xor_sync(FULLM, s_, 4);
                    tv += __shfl_xor_sync(FULLM, tv, 8);
                    tv += __shfl_xor_sync(FULLM, tv, 16);
                }
                float mu = sx * (1.f/256.f);
                float rstd = rsqrtf(fmaf(-mu, mu, sx2*(1.f/256.f)) + 1e-5f);
                float rm = rstd * mu;
                float lgv = fmaf(rstd, tv, fmaf(-rm, qgs_l, qb_l));
                float e = ex2f(lgv);
                float se = e;
                se += __shfl_xor_sync(FULLM, se, 1);
                se += __shfl_xor_sync(FULLM, se, 2);
                se += __shfl_xor_sync(FULLM, se, 4);
                float inv = __fdividef(1.f, se);
                float wv = e * inv;
                float wr = wv * rstd;
                S0 += wv;
                S1v = fmaf(wr, mu, S1v);
                if (lane < 8) wsw[r*8 + tau] = wr;
            }
        }
        if (t > 0){
            const float* xt3 = xs + ((t-1) % 3) * 8192;
            const float* ws3 = ws + ((t-1) & 1) * 256;
            #pragma unroll 4
            for (int rr = 0; rr < 16; rr++){
                int r = rbase + rr;
                float2 wp = *(const float2*)(ws3 + r*8 + s0);
                const float* xrow = xt3 + (r << 8);
                float4 va = *(const float4*)(xrow + fA);
                float4 vb = *(const float4*)(xrow + fB);
                ull xp[4] = { pk2(va.x,va.y), pk2(va.z,va.w), pk2(vb.x,vb.y), pk2(vb.z,vb.w) };
                ull w0 = pk2(wp.x, wp.x), w1 = pk2(wp.y, wp.y);
                #pragma unroll
                for (int j = 0; j < 4; j++){
                    acc0[j] = ffma2(w0, xp[j], acc0[j]);
                    acc1[j] = ffma2(w1, xp[j], acc1[j]);
                }
            }
        }
        __syncthreads();
        if (t + 2 < NT){
            uint32_t dst = xs_sh + ((t+2) % 3) * 32768 + tid16;
            const char* src = (const char*)(gx + (t+2)*TILE*256) + tid16;
            #pragma unroll
            for (int i = 0; i < 8; i++)
                asm volatile("cp.async.cg.shared.global [%0],[%1],16;" :: "r"(dst + i*4096), "l"(src + i*4096));
            asm volatile("cp.async.commit_group;");
        }
    }

    float* mg = smem_f;
    if (warp >= 4){
        float o[8];
        #pragma unroll
        for (int j = 0; j < 4; j++) upk2(acc0[j], o[2*j], o[2*j+1]);
        float* p = mg + ((warp-4)*2 + 0)*256;
        *(float4*)(p + fA) = make_float4(o[0],o[1],o[2],o[3]);
        *(float4*)(p + fB) = make_float4(o[4],o[5],o[6],o[7]);
        #pragma unroll
        for (int j = 0; j < 4; j++) upk2(acc1[j], o[2*j], o[2*j+1]);
        p = mg + ((warp-4)*2 + 1)*256;
        *(float4*)(p + fA) = make_float4(o[0],o[1],o[2],o[3]);
        *(float4*)(p + fB) = make_float4(o[4],o[5],o[6],o[7]);
    }
    if (lane < 8){
        sS[warp*16 + tau*2]     = S0;
        sS[warp*16 + tau*2 + 1] = S1v;
    }
    __syncthreads();
    if (warp < 4){
        const int pbase = ((bv*NCH + chunk) << 3);
        float o[8];
        #pragma unroll
        for (int j = 0; j < 4; j++) upk2(acc0[j], o[2*j], o[2*j+1]);
        const float* pm = mg + (warp*2 + 0)*256;
        {
            float4 a = *(const float4*)(pm + fA), b = *(const float4*)(pm + fB);
            o[0]+=a.x; o[1]+=a.y; o[2]+=a.z; o[3]+=a.w;
            o[4]+=b.x; o[5]+=b.y; o[6]+=b.z; o[7]+=b.w;
        }
        float* dst = d_pacc + ((pbase + s0) << 8);
        *(float4*)(dst + fA) = make_float4(o[0],o[1],o[2],o[3]);
        *(float4*)(dst + fB) = make_float4(o[4],o[5],o[6],o[7]);
        #pragma unroll
        for (int j = 0; j < 4; j++) upk2(acc1[j], o[2*j], o[2*j+1]);
        pm = mg + (warp*2 + 1)*256;
        {
            float4 a = *(const float4*)(pm + fA), b = *(const float4*)(pm + fB);
            o[0]+=a.x; o[1]+=a.y; o[2]+=a.z; o[3]+=a.w;
            o[4]+=b.x; o[5]+=b.y; o[6]+=b.z; o[7]+=b.w;
        }
        dst = d_pacc + ((pbase + s0 + 1) << 8);
        *(float4*)(dst + fA) = make_float4(o[0],o[1],o[2],o[3]);
        *(float4*)(dst + fB) = make_float4(o[4],o[5],o[6],o[7]);
    }
    if (warp == 0 && lane < 8){
        float t0 = 0.f, t1 = 0.f;
        #pragma unroll
        for (int u = 0; u < 8; u++){ t0 += sS[u*16 + lane*2]; t1 += sS[u*16 + lane*2 + 1]; }
        int idx = ((bv*NCH + chunk)*8 + lane)*2;
        d_psc[idx] = t0; d_psc[idx+1] = t1;
    }
}

__global__ void k_combine(const float* __restrict__ g, const float* __restrict__ bb)
{
    int r = blockIdx.x, bv = r >> 3, s = r & 7, f = threadIdx.x;
    const float* pa = d_pacc + ((bv*NCH*8 + s) << 8) + f;
    float X = 0.f;
    #pragma unroll
    for (int c = 0; c < NCH; c++) X += pa[c * 2048];
    const float* ps = d_psc + (bv*NCH*8 + s)*2;
    float s0 = 0.f, s1 = 0.f;
    #pragma unroll
    for (int c = 0; c < NCH; c++){ s0 += ps[c*16]; s1 += ps[c*16+1]; }
    float inv = __fdividef(1.f, s0);
    d_Y[(r << 8) + f] = fmaf(g[f], (X - s1) * inv, bb[f]);
}

// 32x64 GEMM, 128 threads, 4x4/thread, register-prefetch pipelined K-loop
template<int TRANSB, int RELU>
__global__ void __launch_bounds__(128)
k_gemm(int M, int N, int K,
       const float* __restrict__ A, int lda,
       const float* __restrict__ B, int ldb,
       float* __restrict__ C, int ldc,
       const float* __restrict__ bias,
       const float* __restrict__ resid, int ldr, float alpha)
{
    __shared__ __align__(16) float As[32][36];
    __shared__ __align__(16) float Bs[32][68];
    const int bm = blockIdx.y * 32, bn = blockIdx.x * 64;
    const int tid = threadIdx.x, tx = tid & 15, ty = tid >> 4;
    float acc[4][4] = {};

    const int am = tid & 31, ak8 = (tid >> 5) << 3;
    const float* aptr = A + (size_t)(bm + am)*lda + ak8;
    const int bn1 = tid >> 1, bkc = (tid & 1) << 4;
    const int bkk = tid >> 2, bnc = (tid & 3) << 4;
    const float* bptr = TRANSB ? (B + (size_t)(bn + bn1)*ldb + bkc)
                               : (B + (size_t)bkk*ldb + bn + bnc);

    float4 pa0, pa1, pb[4];
    pa0 = *(const float4*)aptr; pa1 = *(const float4*)(aptr + 4);
    #pragma unroll
    for (int j = 0; j < 4; j++) pb[j] = *(const float4*)(bptr + j*4);

    const int KT = K >> 5;
    for (int t = 0; t < KT; t++){
        As[ak8+0][am]=pa0.x; As[ak8+1][am]=pa0.y; As[ak8+2][am]=pa0.z; As[ak8+3][am]=pa0.w;
        As[ak8+4][am]=pa1.x; As[ak8+5][am]=pa1.y; As[ak8+6][am]=pa1.z; As[ak8+7][am]=pa1.w;
        if (TRANSB){
            #pragma unroll
            for (int j = 0; j < 4; j++){
                Bs[bkc+j*4+0][bn1]=pb[j].x; Bs[bkc+j*4+1][bn1]=pb[j].y;
                Bs[bkc+j*4+2][bn1]=pb[j].z; Bs[bkc+j*4+3][bn1]=pb[j].w;
            }
        } else {
            #pragma unroll
            for (int j = 0; j < 4; j++)
                *(float4*)&Bs[bkk][bnc + j*4] = pb[j];
        }
        __syncthreads();
        if (t + 1 < KT){
            const float* an = aptr + (t+1)*32;
            pa0 = *(const float4*)an; pa1 = *(const float4*)(an + 4);
            if (TRANSB){
                const float* bn_ = bptr + (t+1)*32;
                #pragma unroll
                for (int j = 0; j < 4; j++) pb[j] = *(const float4*)(bn_ + j*4);
            } else {
                const float* bn_ = bptr + (size_t)(t+1)*32*ldb;
                #pragma unroll
                for (int j = 0; j < 4; j++) pb[j] = *(const float4*)(bn_ + j*4);
            }
        }
        #pragma unroll
        for (int kk = 0; kk < 32; kk++){
            float4 a = *(const float4*)&As[kk][ty << 2];
            float4 b = *(const float4*)&Bs[kk][tx << 2];
            float av[4] = {a.x,a.y,a.z,a.w}, bv[4] = {b.x,b.y,b.z,b.w};
            #pragma unroll
            for (int i = 0; i < 4; i++)
                #pragma unroll
                for (int j = 0; j < 4; j++)
                    acc[i][j] = fmaf(av[i], bv[j], acc[i][j]);
        }
        __syncthreads();
    }
    #pragma unroll
    for (int i = 0; i < 4; i++){
        int row = bm + (ty << 2) + i;
        int col = bn + (tx << 2);
        float4 v = make_float4(acc[i][0]*alpha, acc[i][1]*alpha, acc[i][2]*alpha, acc[i][3]*alpha);
        if (bias){
            float4 bb4 = *(const float4*)(bias + col);
            v.x += bb4.x; v.y += bb4.y; v.z += bb4.z; v.w += bb4.w;
        }
        if (resid){
            float4 rr4 = *(const float4*)(resid + (size_t)row*ldr + col);
            v.x += rr4.x; v.y += rr4.y; v.z += rr4.z; v.w += rr4.w;
        }
        if (RELU){
            v.x = fmaxf(v.x, 0.f); v.y = fmaxf(v.y, 0.f);
            v.z = fmaxf(v.z, 0.f); v.w = fmaxf(v.w, 0.f);
        }
        *(float4*)(C + (size_t)row*ldc + col) = v;
    }
}

// 32x32 GEMM, 128 threads, 2x4/thread, register-prefetch pipelined (TRANSB=0 only)
template<int RELU>
__global__ void __launch_bounds__(128)
k_gemm32(int M, int N, int K,
         const float* __restrict__ A, int lda,
         const float* __restrict__ B, int ldb,
         float* __restrict__ C, int ldc,
         const float* __restrict__ bias,
         const float* __restrict__ resid, int ldr)
{
    __shared__ __align__(16) float As[32][36];
    __shared__ __align__(16) float Bs[32][36];
    const int bm = blockIdx.y * 32, bn = blockIdx.x * 32;
    const int tid = threadIdx.x, tx = tid & 7, ty = tid >> 3;
    float acc[2][4] = {};

    const int am = tid & 31, ak8 = (tid >> 5) << 3;
    const float* aptr = A + (size_t)(bm + am)*lda + ak8;
    const int bkk = tid >> 2, bnc = (tid & 3) << 3;
    const float* bptr = B + (size_t)bkk*ldb + bn + bnc;

    float4 pa0, pa1, pb0, pb1;
    pa0 = *(const float4*)aptr; pa1 = *(const float4*)(aptr + 4);
    pb0 = *(const float4*)bptr; pb1 = *(const float4*)(bptr + 4);

    const int KT = K >> 5;
    for (int t = 0; t < KT; t++){
        As[ak8+0][am]=pa0.x; As[ak8+1][am]=pa0.y; As[ak8+2][am]=pa0.z; As[ak8+3][am]=pa0.w;
        As[ak8+4][am]=pa1.x; As[ak8+5][am]=pa1.y; As[ak8+6][am]=pa1.z; As[ak8+7][am]=pa1.w;
        *(float4*)&Bs[bkk][bnc]     = pb0;
        *(float4*)&Bs[bkk][bnc + 4] = pb1;
        __syncthreads();
        if (t + 1 < KT){
            const float* an = aptr + (t+1)*32;
            pa0 = *(const float4*)an; pa1 = *(const float4*)(an + 4);
            const float* bn_ = bptr + (size_t)(t+1)*32*ldb;
            pb0 = *(const float4*)bn_; pb1 = *(const float4*)(bn_ + 4);
        }
        #pragma unroll
        for (int kk = 0; kk < 32; kk++){
            float2 a = *(const float2*)&As[kk][ty << 1];
            float4 b = *(const float4*)&Bs[kk][tx << 2];
            float bv[4] = {b.x,b.y,b.z,b.w};
            #pragma unroll
            for (int j = 0; j < 4; j++){
                acc[0][j] = fmaf(a.x, bv[j], acc[0][j]);
                acc[1][j] = fmaf(a.y, bv[j], acc[1][j]);
            }
        }
        __syncthreads();
    }
    #pragma unroll
    for (int i = 0; i < 2; i++){
        int row = bm + (ty << 1) + i;
        int col = bn + (tx << 2);
        float4 v = make_float4(acc[i][0], acc[i][1], acc[i][2], acc[i][3]);
        if (bias){
            float4 bb4 = *(const float4*)(bias + col);
            v.x += bb4.x; v.y += bb4.y; v.z += bb4.z; v.w += bb4.w;
        }
        if (resid){
            float4 rr4 = *(const float4*)(resid + (size_t)row*ldr + col);
            v.x += rr4.x; v.y += rr4.y; v.z += rr4.z; v.w += rr4.w;
        }
        if (RELU){
            v.x = fmaxf(v.x, 0.f); v.y = fmaxf(v.y, 0.f);
            v.z = fmaxf(v.z, 0.f); v.w = fmaxf(v.w, 0.f);
        }
        *(float4*)(C + (size_t)row*ldc + col) = v;
    }
}

// z-batched dual GEMM, 128 threads, 32x64, register-prefetch pipelined (R15 proven)
__global__ void __launch_bounds__(128)
k_gemm_dual(const float* __restrict__ A0, const float* __restrict__ B0,
            float* __restrict__ C0, const float* __restrict__ bias0,
            const float* __restrict__ A1, const float* __restrict__ B1,
            float* __restrict__ C1, const float* __restrict__ bias1)
{
    const int z = blockIdx.z;
    const float* A = z ? A1 : A0;
    const float* B = z ? B1 : B0;
    float* C = z ? C1 : C0;
    const float* bias = z ? bias1 : bias0;
    const int lda = 256, ldb = 768, ldc = 768;

    __shared__ __align__(16) float As[32][36];
    __shared__ __align__(16) float Bs[32][68];
    const int bm = blockIdx.y * 32, bn = blockIdx.x * 64;
    const int tid = threadIdx.x, tx = tid & 15, ty = tid >> 4;
    float acc[4][4] = {};

    const int am = tid & 31, ak8 = (tid >> 5) << 3;
    const float* aptr = A + (size_t)(bm + am)*lda + ak8;
    const int bkk = tid >> 2, bnc = (tid & 3) << 4;
    const float* bptr = B + (size_t)bkk*ldb + bn + bnc;

    float4 pa0, pa1, pb[4];
    pa0 = *(const float4*)aptr; pa1 = *(const float4*)(aptr + 4);
    #pragma unroll
    for (int j = 0; j < 4; j++) pb[j] = *(const float4*)(bptr + j*4);

    for (int t = 0; t < 8; t++){
        As[ak8+0][am]=pa0.x; As[ak8+1][am]=pa0.y; As[ak8+2][am]=pa0.z; As[ak8+3][am]=pa0.w;
        As[ak8+4][am]=pa1.x; As[ak8+5][am]=pa1.y; As[ak8+6][am]=pa1.z; As[ak8+7][am]=pa1.w;
        #pragma unroll
        for (int j = 0; j < 4; j++)
            *(float4*)&Bs[bkk][bnc + j*4] = pb[j];
        __syncthreads();
        if (t + 1 < 8){
            const float* an = aptr + (t+1)*32;
            pa0 = *(const float4*)an; pa1 = *(const float4*)(an + 4);
            const float* bn_ = bptr + (size_t)(t+1)*32*ldb;
            #pragma unroll
            for (int j = 0; j < 4; j++) pb[j] = *(const float4*)(bn_ + j*4);
        }
        #pragma unroll
        for (int kk = 0; kk < 32; kk++){
            float4 a = *(const float4*)&As[kk][ty << 2];
            float4 b = *(const float4*)&Bs[kk][tx << 2];
            float av[4] = {a.x,a.y,a.z,a.w}, bv[4] = {b.x,b.y,b.z,b.w};
            #pragma unroll
            for (int i = 0; i < 4; i++)
                #pragma unroll
                for (int j = 0; j < 4; j++)
                    acc[i][j] = fmaf(av[i], bv[j], acc[i][j]);
        }
        __syncthreads();
    }
    #pragma unroll
    for (int i = 0; i < 4; i++){
        int row = bm + (ty << 2) + i;
        int col = bn + (tx << 2);
        float4 bb4 = *(const float4*)(bias + col);
        float4 v = make_float4(acc[i][0]+bb4.x, acc[i][1]+bb4.y, acc[i][2]+bb4.z, acc[i][3]+bb4.w);
        *(float4*)(C + (size_t)row*ldc + col) = v;
    }
}

__global__ void k_gru(const float* __restrict__ g, const float* __restrict__ bb)
{
    int r = blockIdx.x * 4 + (threadIdx.x >> 5);
    int lane = threadIdx.x & 31, f0 = lane << 3;
    int base = r * 768;
    float gi0[8], gi1[8], gi2[8], gh0[8], gh1[8], gh2[8], hv[8];
    #pragma unroll
    for (int c = 0; c < 2; c++){
        float4 t;
        t = *(const float4*)(d_gi + base + f0 + c*4);        gi0[c*4]=t.x; gi0[c*4+1]=t.y; gi0[c*4+2]=t.z; gi0[c*4+3]=t.w;
        t = *(const float4*)(d_gi + base + 256 + f0 + c*4);  gi1[c*4]=t.x; gi1[c*4+1]=t.y; gi1[c*4+2]=t.z; gi1[c*4+3]=t.w;
        t = *(const float4*)(d_gi + base + 512 + f0 + c*4);  gi2[c*4]=t.x; gi2[c*4+1]=t.y; gi2[c*4+2]=t.z; gi2[c*4+3]=t.w;
        t = *(const float4*)(d_gh + base + f0 + c*4);        gh0[c*4]=t.x; gh0[c*4+1]=t.y; gh0[c*4+2]=t.z; gh0[c*4+3]=t.w;
        t = *(const float4*)(d_gh + base + 256 + f0 + c*4);  gh1[c*4]=t.x; gh1[c*4+1]=t.y; gh1[c*4+2]=t.z; gh1[c*4+3]=t.w;
        t = *(const float4*)(d_gh + base + 512 + f0 + c*4);  gh2[c*4]=t.x; gh2[c*4+1]=t.y; gh2[c*4+2]=t.z; gh2[c*4+3]=t.w;
        t = *(const float4*)(d_h + (r << 8) + f0 + c*4);     hv[c*4]=t.x; hv[c*4+1]=t.y; hv[c*4+2]=t.z; hv[c*4+3]=t.w;
    }
    float xm[8], sx = 0.f, sx2 = 0.f;
    #pragma unroll
    for (int i = 0; i < 8; i++){
        float rg = sigf(gi0[i] + gh0[i]);
        float z  = sigf(gi1[i] + gh1[i]);
        float nn = tanhf_a(fmaf(rg, gh2[i], gi2[i]));
        xm[i] = fmaf(z, hv[i], (1.f - z) * nn);
        sx += xm[i]; sx2 = fmaf(xm[i], xm[i], sx2);
    }
    float4* xp = (float4*)(d_xmain + (r << 8) + f0);
    xp[0] = make_float4(xm[0],xm[1],xm[2],xm[3]);
    xp[1] = make_float4(xm[4],xm[5],xm[6],xm[7]);
    warp_red2(sx, sx2);
    float mu = sx * (1.f/256.f);
    float rstd = rsqrtf(fmaf(-mu, mu, sx2*(1.f/256.f)) + 1e-5f);
    const float4* gp = (const float4*)(g + f0);
    const float4* bp = (const float4*)(bb + f0);
    float4 ga = gp[0], gb2 = gp[1], ba = bp[0], bb2 = bp[1];
    float gg[8] = {ga.x,ga.y,ga.z,ga.w,gb2.x,gb2.y,gb2.z,gb2.w};
    float bv[8] = {ba.x,ba.y,ba.z,ba.w,bb2.x,bb2.y,bb2.z,bb2.w};
    float o[8];
    #pragma unroll
    for (int i = 0; i < 8; i++) o[i] = fmaf((xm[i]-mu)*rstd, gg[i], bv[i]);
    float4* lp = (float4*)(d_lnm + (r << 8) + f0);
    lp[0] = make_float4(o[0],o[1],o[2],o[3]);
    lp[1] = make_float4(o[4],o[5],o[6],o[7]);
}

__global__ void k_reduce(float* dst_view, float* dst_attr)
{
    int i = blockIdx.x * 256 + threadIdx.x;
    if (i < BV_*64){
        int bv = i >> 6, f = i & 63;
        float sum = 0.f;
        #pragma unroll
        for (int s = 0; s < 8; s++) sum += d_sfull[(((bv<<3)+s) << 8) + f];
        dst_view[i] = sum * 0.125f;
    } else {
        int j = i - BV_*64;
        if (j < B_*8*192){
            int bs = j / 192, f = j % 192;
            int b = bs >> 3, s = bs & 7;
            float sum = 0.f;
            #pragma unroll
            for (int v = 0; v < 4; v++) sum += d_sfull[(((b*4+v)*8+s) << 8) + 64 + f];
            dst_attr[j] = sum * 0.25f;
        }
    }
}

extern "C" void kernel_launch(void* const* d_in, const int* in_sizes, int n_in,
                              void* d_out, int out_size)
{
    (void)in_sizes; (void)n_in; (void)out_size;
    const float* x   = (const float*)d_in[0];
    const float* nv  = (const float*)d_in[1];
    const float* na  = (const float*)d_in[2];
    const float* vl  = (const float*)d_in[3];
    const float* vs  = (const float*)d_in[4];
    const float* al  = (const float*)d_in[5];
    const float* as_ = (const float*)d_in[6];
    const float* ln_kv_g = (const float*)d_in[7];
    const float* ln_kv_b = (const float*)d_in[8];
    const float* W_kv    = (const float*)d_in[9];
    const float* ln_q_g  = (const float*)d_in[10];
    const float* ln_q_b  = (const float*)d_in[11];
    const float* W_qry   = (const float*)d_in[12];
    const float* w_ih    = (const float*)d_in[13];
    const float* w_hh    = (const float*)d_in[14];
    const float* b_ih    = (const float*)d_in[15];
    const float* b_hh    = (const float*)d_in[16];
    const float* ln_r_g  = (const float*)d_in[17];
    const float* ln_r_b  = (const float*)d_in[18];
    const float* W_r1    = (const float*)d_in[19];
    const float* b_r1    = (const float*)d_in[20];
    const float* W_r2    = (const float*)d_in[21];
    const float* b_r2    = (const float*)d_in[22];
    float* out_view = (float*)d_out;
    float* out_attr = out_view + BV_*64;

    float* Mq;    cudaGetSymbolAddress((void**)&Mq, d_Mq);
    float* Wf;    cudaGetSymbolAddress((void**)&Wf, d_Wf);
    float* whhT;  cudaGetSymbolAddress((void**)&whhT, d_whhT);
    float* Y;     cudaGetSymbolAddress((void**)&Y, d_Y);
    float* gi;    cudaGetSymbolAddress((void**)&gi, d_gi);
    float* gh;    cudaGetSymbolAddress((void**)&gh, d_gh);
    float* h;     cudaGetSymbolAddress((void**)&h, d_h);
    float* lnm;   cudaGetSymbolAddress((void**)&lnm, d_lnm);
    float* t1;    cudaGetSymbolAddress((void**)&t1, d_t1);
    float* sfull; cudaGetSymbolAddress((void**)&sfull, d_sfull);
    float* xmain; cudaGetSymbolAddress((void**)&xmain, d_xmain);

    const int FLASH_SMEM = (24576 + 512 + 128) * 4;
    static int smem_set = 0;
    if (!smem_set){
        cudaFuncSetAttribute(k_flash, cudaFuncAttributeMaxDynamicSharedMemorySize, FLASH_SMEM);
        smem_set = 1;
    }

    const float coef = 0.08838834764831845f;   // 1/sqrt(128)

    k_init<<<112,256>>>(nv, na, vl, vs, al, as_);
    k_gemm<1,0><<<dim3(4,8),128>>>(256,256,128, W_qry,128, W_kv,384, Mq,256, nullptr, nullptr,0, coef);

    for (int step = 0; step < 3; step++){
        k_qfused<<<128,256>>>(ln_q_g, ln_q_b, ln_kv_g, ln_kv_b, step > 0 ? 1 : 0);
        k_flash<<<dim3(NCH,64),256,FLASH_SMEM>>>(x);
        if (step == 0){
            k_gemm<1,0><<<dim3(12,8),128>>>(256,768,256, W_kv+128,384, w_ih,256, Wf,768, nullptr, nullptr,0, 1.f);
            k_transpose<<<dim3(8,24),256>>>(w_hh, whhT, 768, 256);
        }
        k_combine<<<512,256>>>(ln_kv_g, ln_kv_b);
        k_gemm_dual<<<dim3(12,16,2),128>>>(Y, Wf, gi, b_ih, h, whhT, gh, b_hh);
        k_gru<<<128,128>>>(ln_r_g, ln_r_b);
        k_gemm32<1><<<dim3(16,16),128>>>(512,512,256, lnm,256, W_r1,512, t1,512, b_r1, nullptr,0);
        k_gemm32<0><<<dim3(8,16),128>>>(512,256,512, t1,512, W_r2,256, sfull,256, b_r2, xmain,256);
    }
    k_reduce<<<112,256>>>(out_view, out_attr);
}